// round 14
// baseline (speedup 1.0000x reference)
#include <cuda_runtime.h>
#include <cuda_bf16.h>
#include <cstdint>

#define G_NUM   32
#define N_ROWS  2048
#define STRA    272                     // A smem row stride bytes (128 k * 2B + 16 pad)
#define STRBB   144                     // B smem row stride bytes (64 n * 2B + 16 pad)
#define SAHI    0
#define SALO    (64 * STRA)             // 17408
#define SBHI    (2 * 64 * STRA)         // 34816
#define SBLO    (SBHI + 128 * STRBB)    // 53248
#define SMEM_GEMM (SBLO + 128 * STRBB)  // 71680 -> 3 CTAs/SM

// ---------------- helpers ----------------
static __device__ __forceinline__ uint32_t smem_u32(const void* p) {
    uint32_t a;
    asm("{ .reg .u64 t; cvta.to.shared.u64 t, %1; cvt.u32.u64 %0, t; }" : "=r"(a) : "l"(p));
    return a;
}
static __device__ __forceinline__ void ldmx4(uint32_t* r, uint32_t addr) {
    asm volatile("ldmatrix.sync.aligned.m8n8.x4.shared.b16 {%0,%1,%2,%3}, [%4];"
                 : "=r"(r[0]), "=r"(r[1]), "=r"(r[2]), "=r"(r[3]) : "r"(addr));
}
static __device__ __forceinline__ void ldmx4t(uint32_t* r, uint32_t addr) {
    asm volatile("ldmatrix.sync.aligned.m8n8.x4.trans.shared.b16 {%0,%1,%2,%3}, [%4];"
                 : "=r"(r[0]), "=r"(r[1]), "=r"(r[2]), "=r"(r[3]) : "r"(addr));
}
static __device__ __forceinline__ void mma16816(float* c, const uint32_t* a, const uint32_t* b) {
    asm volatile(
        "mma.sync.aligned.m16n8k16.row.col.f32.bf16.bf16.f32 "
        "{%0,%1,%2,%3}, {%4,%5,%6,%7}, {%8,%9}, {%0,%1,%2,%3};"
        : "+f"(c[0]), "+f"(c[1]), "+f"(c[2]), "+f"(c[3])
        : "r"(a[0]), "r"(a[1]), "r"(a[2]), "r"(a[3]), "r"(b[0]), "r"(b[1]));
}
static __device__ __forceinline__ uint32_t pack_split(float v0, float v1, uint32_t& lo_pack) {
    __nv_bfloat16 h0 = __float2bfloat16(v0);
    __nv_bfloat16 h1 = __float2bfloat16(v1);
    __nv_bfloat16 l0 = __float2bfloat16(v0 - __bfloat162float(h0));
    __nv_bfloat16 l1 = __float2bfloat16(v1 - __bfloat162float(h1));
    __nv_bfloat162 hp(h0, h1), lp(l0, l1);
    lo_pack = *reinterpret_cast<uint32_t*>(&lp);
    return *reinterpret_cast<uint32_t*>(&hp);
}

// ---------------- GEMM tile: M64 x N64, K=128, split-bf16 3-pass ----------------
// Y[mi, o] = sum_m X[mi, m] * (alpha * W[m, o]),  mi = local_row*D + i.
// This block handles output columns [nh*64, nh*64+64).
template <int D>
__device__ __forceinline__ void run_tile(char* smem, uint32_t smem_base,
                                         const float* __restrict__ x,
                                         const float* __restrict__ wg,
                                         const int* __restrict__ rep,
                                         float* __restrict__ y,
                                         int g, int t, int nh)
{
    const int tid  = threadIdx.x;
    const int wid  = tid >> 5;
    const int lane = tid & 31;

    // ---- warp-redundant prefix scan of repeats ----
    const int rv = rep[lane];
    int incl = rv;
    #pragma unroll
    for (int d = 1; d < 32; d <<= 1) {
        const int s = __shfl_up_sync(0xffffffffu, incl, d);
        if (lane >= d) incl += s;
    }
    const int rows      = __shfl_sync(0xffffffffu, rv, g);
    const int row_begin = __shfl_sync(0xffffffffu, incl, g) - rows;

    const int Mg  = rows * D;
    const int mi0 = t * 64;
    if (mi0 >= Mg) return;
    const int valid = min(64, Mg - mi0);

    // ---- warp-specialized staging: warps 0-2 stage B (half-W), warps 3-7 stage A ----
    if (tid < 96) {
        // B: W fp32 [m][o-half] -> split bf16 [k=m][n], float4 LDG
        const float* wcol = wg + nh * 64;
        #pragma unroll 4
        for (int e = tid; e < 2048; e += 96) {       // e = m*16 + o4
            const int m = e >> 4, o4 = e & 15;
            const float4 v = *(const float4*)(wcol + m * 128 + 4 * o4);
            uint32_t lp0, hp0 = pack_split(v.x * 0.015625f, v.y * 0.015625f, lp0);
            uint32_t lp1, hp1 = pack_split(v.z * 0.015625f, v.w * 0.015625f, lp1);
            *(uint2*)(smem + SBHI + m * STRBB + o4 * 8) = make_uint2(hp0, hp1);
            *(uint2*)(smem + SBLO + m * STRBB + o4 * 8) = make_uint2(lp0, lp1);
        }
    } else {
        // A: X tile -> split bf16 [mi][k], 160 threads
        const int tid2 = tid - 96;
        #pragma unroll 4
        for (int e = tid2; e < 4096; e += 160) {     // e = mi_l*64 + k2
            const int mi_l = e >> 6;
            const int k2   = e & 63;
            float v0 = 0.f, v1 = 0.f;
            if (mi_l < valid) {
                const int mi = mi0 + mi_l;
                const int r  = mi / D;
                const int i  = mi - r * D;
                const float* xr = x + ((size_t)(row_begin + r) * 128) * D + i;
                v0 = xr[(2 * k2) * D];
                v1 = xr[(2 * k2 + 1) * D];
            }
            uint32_t lp, hp = pack_split(v0, v1, lp);
            *(uint32_t*)(smem + SAHI + mi_l * STRA + k2 * 4) = hp;
            *(uint32_t*)(smem + SALO + mi_l * STRA + k2 * 4) = lp;
        }
    }
    __syncthreads();

    // ---- warp tiling: 2(M) x 4(N) warps, each M32 x N16 ----
    const int mwarp = (wid >> 2) * 32;
    const int nwarp = (wid & 3) * 16;

    float acc[2][2][4];
    #pragma unroll
    for (int a = 0; a < 2; ++a)
        #pragma unroll
        for (int b = 0; b < 2; ++b)
            #pragma unroll
            for (int c = 0; c < 4; ++c) acc[a][b][c] = 0.f;

    const uint32_t aHi = smem_base + SAHI
        + (mwarp + (lane & 7) + ((lane >> 3) & 1) * 8) * STRA + (lane >> 4) * 16;
    const uint32_t bHi = smem_base + SBHI
        + (lane & 15) * STRBB + (nwarp + (lane >> 4) * 8) * 2;

    #pragma unroll
    for (int k = 0; k < 8; ++k) {
        const uint32_t kofA = k * 32;           // +k16 along A cols = 32B
        const uint32_t kofB = k * 16 * STRBB;   // +k16 along B rows
        uint32_t ah[2][4], al[2][4], bh[4], bl[4];
        ldmx4(ah[0], aHi + kofA);
        ldmx4(ah[1], aHi + 16 * STRA + kofA);
        ldmx4(al[0], aHi + SALO + kofA);
        ldmx4(al[1], aHi + SALO + 16 * STRA + kofA);
        ldmx4t(bh, bHi + kofB);                 // n-tiles {0:8, 8:16}
        ldmx4t(bl, bHi + (SBLO - SBHI) + kofB);
        // pass-major order: independent accumulators between c reuses
        #pragma unroll
        for (int p = 0; p < 3; ++p) {
            #pragma unroll
            for (int m2 = 0; m2 < 2; ++m2) {
                const uint32_t* ap = (p == 2) ? al[m2] : ah[m2];
                #pragma unroll
                for (int j = 0; j < 2; ++j) {
                    const uint32_t* bp = (p == 1) ? &bl[j * 2] : &bh[j * 2];
                    mma16816(acc[m2][j], ap, bp);
                }
            }
        }
    }

    // ---- epilogue: direct scatter to y (R10-proven) ----
    #pragma unroll
    for (int m2 = 0; m2 < 2; ++m2) {
        const int rbase = mwarp + 16 * m2 + (lane >> 2);
        #pragma unroll
        for (int h = 0; h < 2; ++h) {
            const int mi_l = rbase + 8 * h;
            if (mi_l < valid) {
                const int mi = mi0 + mi_l;
                const int r  = mi / D;
                const int i  = mi - r * D;
                float* yr = y + ((size_t)(row_begin + r) * 128) * D + i;
                #pragma unroll
                for (int nb = 0; nb < 2; ++nb) {
                    const int o = nh * 64 + nwarp + 8 * nb + 2 * (lane & 3);
                    yr[(size_t)o * D]       = acc[m2][nb][2 * h + 0];
                    yr[(size_t)(o + 1) * D] = acc[m2][nb][2 * h + 1];
                }
            }
        }
    }
}

__global__ __launch_bounds__(256, 3)
void ilin_mma(const float* __restrict__ x0, const float* __restrict__ x1,
              const float* __restrict__ x2, const float* __restrict__ w,
              const int* __restrict__ rep, float* __restrict__ y)
{
    extern __shared__ char smem[];
    const uint32_t smem_base = smem_u32(smem);
    const int g = blockIdx.x;
    const int z = blockIdx.y;   // 0-3: d1 (2 tiles x 2 nh) | 4-15: d3 (6x2) | 16-35: d5 (10x2)

    const float* wg = w + (size_t)g * 49152;
    if (z < 4) {
        run_tile<1>(smem, smem_base, x0, wg, rep, y, g, z >> 1, z & 1);
    } else if (z < 16) {
        const int zz = z - 4;
        run_tile<3>(smem, smem_base, x1, wg + 16384, rep,
                    y + (size_t)N_ROWS * 128, g, zz >> 1, zz & 1);
    } else {
        const int zz = z - 16;
        run_tile<5>(smem, smem_base, x2, wg + 32768, rep,
                    y + (size_t)N_ROWS * 512, g, zz >> 1, zz & 1);
    }
}

extern "C" void kernel_launch(void* const* d_in, const int* in_sizes, int n_in,
                              void* d_out, int out_size)
{
    const float* x0  = (const float*)d_in[0];   // (N, 128, 1)
    const float* x1  = (const float*)d_in[1];   // (N, 128, 3)
    const float* x2  = (const float*)d_in[2];   // (N, 128, 5)
    const float* w   = (const float*)d_in[3];   // (32, 49152)
    const int*   rep = (const int*)d_in[4];     // (32,)
    float* y = (float*)d_out;

    cudaFuncSetAttribute(ilin_mma, cudaFuncAttributeMaxDynamicSharedMemorySize, SMEM_GEMM);
    ilin_mma<<<dim3(G_NUM, 36), 256, SMEM_GEMM>>>(x0, x1, x2, w, rep, y);
}

// round 15
// speedup vs baseline: 1.2339x; 1.2339x over previous
#include <cuda_runtime.h>
#include <cuda_bf16.h>
#include <cstdint>

#define G_NUM   32
#define N_ROWS  2048
#define STRB    272                     // smem row stride in bytes (136 bf16) -> conflict-free
#define SAHI    0
#define SALO    (64 * STRB)             // 17408
#define SBHI    (2 * 64 * STRB)         // 34816
#define SBLO    (SBHI + 128 * STRB)     // 69632
#define SMEM_GEMM (SBLO + 128 * STRB)   // 104448 -> 2 CTAs/SM

// ---------------- helpers ----------------
static __device__ __forceinline__ uint32_t smem_u32(const void* p) {
    uint32_t a;
    asm("{ .reg .u64 t; cvta.to.shared.u64 t, %1; cvt.u32.u64 %0, t; }" : "=r"(a) : "l"(p));
    return a;
}
static __device__ __forceinline__ void ldmx4(uint32_t* r, uint32_t addr) {
    asm volatile("ldmatrix.sync.aligned.m8n8.x4.shared.b16 {%0,%1,%2,%3}, [%4];"
                 : "=r"(r[0]), "=r"(r[1]), "=r"(r[2]), "=r"(r[3]) : "r"(addr));
}
static __device__ __forceinline__ void ldmx4t(uint32_t* r, uint32_t addr) {
    asm volatile("ldmatrix.sync.aligned.m8n8.x4.trans.shared.b16 {%0,%1,%2,%3}, [%4];"
                 : "=r"(r[0]), "=r"(r[1]), "=r"(r[2]), "=r"(r[3]) : "r"(addr));
}
static __device__ __forceinline__ void mma16816(float* c, const uint32_t* a, const uint32_t* b) {
    asm volatile(
        "mma.sync.aligned.m16n8k16.row.col.f32.bf16.bf16.f32 "
        "{%0,%1,%2,%3}, {%4,%5,%6,%7}, {%8,%9}, {%0,%1,%2,%3};"
        : "+f"(c[0]), "+f"(c[1]), "+f"(c[2]), "+f"(c[3])
        : "r"(a[0]), "r"(a[1]), "r"(a[2]), "r"(a[3]), "r"(b[0]), "r"(b[1]));
}
// Dekker truncation split: hi = v with mantissa truncated to bf16 (top 16 bits),
// lo = rn_bf16(v - hi) where the subtraction is EXACT in fp32.
// hi pair packed with a single PRMT (bytes 2,3 of v0 | bytes 2,3 of v1).
static __device__ __forceinline__ uint32_t pack_split_t(float v0, float v1, uint32_t& lo_pack) {
    const uint32_t u0 = __float_as_uint(v0), u1 = __float_as_uint(v1);
    uint32_t hp;
    asm("prmt.b32 %0, %1, %2, 0x7632;" : "=r"(hp) : "r"(u0), "r"(u1));
    const float h0 = __uint_as_float(u0 & 0xFFFF0000u);
    const float h1 = __uint_as_float(u1 & 0xFFFF0000u);
    const float l0 = v0 - h0;            // exact
    const float l1 = v1 - h1;            // exact
    asm("cvt.rn.bf16x2.f32 %0, %1, %2;" : "=r"(lo_pack) : "f"(l1), "f"(l0));  // {hi=l1, lo=l0}
    return hp;
}

// ---------------- GEMM tile: M64 x N128, K=128, split-bf16 3-pass ----------------
// Y[mi, o] = sum_m X[mi, m] * (alpha * W[m, o]),  mi = local_row*D + i.
template <int D>
__device__ __forceinline__ void run_tile(char* smem, uint32_t smem_base,
                                         const float* __restrict__ x,
                                         const float* __restrict__ wg,
                                         const int* __restrict__ rep,
                                         float* __restrict__ y,
                                         int g, int t)
{
    const int tid  = threadIdx.x;
    const int wid  = tid >> 5;
    const int lane = tid & 31;

    // ---- warp-redundant prefix scan of repeats ----
    const int rv = rep[lane];
    int incl = rv;
    #pragma unroll
    for (int d = 1; d < 32; d <<= 1) {
        const int s = __shfl_up_sync(0xffffffffu, incl, d);
        if (lane >= d) incl += s;
    }
    const int rows      = __shfl_sync(0xffffffffu, rv, g);
    const int row_begin = __shfl_sync(0xffffffffu, incl, g) - rows;

    const int Mg  = rows * D;
    const int mi0 = t * 64;
    if (mi0 >= Mg) return;
    const int valid = min(64, Mg - mi0);

    // ---- warp-specialized staging: warps 0-3 stage B, warps 4-7 stage A ----
    if (wid < 4) {
        // B: W fp32 [m][o] -> split bf16 [k=m][n=o], float4 LDG, 128 threads
        #pragma unroll 8
        for (int e = tid; e < 4096; e += 128) {      // e = m*32 + o4
            const int m = e >> 5, o4 = e & 31;
            const float4 v = *(const float4*)(wg + m * 128 + 4 * o4);
            uint32_t lp0, hp0 = pack_split_t(v.x * 0.015625f, v.y * 0.015625f, lp0);
            uint32_t lp1, hp1 = pack_split_t(v.z * 0.015625f, v.w * 0.015625f, lp1);
            *(uint2*)(smem + SBHI + m * STRB + o4 * 8) = make_uint2(hp0, hp1);
            *(uint2*)(smem + SBLO + m * STRB + o4 * 8) = make_uint2(lp0, lp1);
        }
    } else {
        // A: X tile -> split bf16 [mi][k], 128 threads
        const int tid2 = tid - 128;
        #pragma unroll 8
        for (int e = tid2; e < 4096; e += 128) {     // e = mi_l*64 + k2
            const int mi_l = e >> 6;
            const int k2   = e & 63;
            float v0 = 0.f, v1 = 0.f;
            if (mi_l < valid) {
                const int mi = mi0 + mi_l;
                const int r  = mi / D;
                const int i  = mi - r * D;
                const float* xr = x + ((size_t)(row_begin + r) * 128) * D + i;
                v0 = xr[(2 * k2) * D];
                v1 = xr[(2 * k2 + 1) * D];
            }
            uint32_t lp, hp = pack_split_t(v0, v1, lp);
            *(uint32_t*)(smem + SAHI + mi_l * STRB + k2 * 4) = hp;
            *(uint32_t*)(smem + SALO + mi_l * STRB + k2 * 4) = lp;
        }
    }
    __syncthreads();

    // ---- warp tiling: 2(M) x 4(N) warps, each M32 x N32 ----
    const int mwarp = (wid >> 2) * 32;
    const int nwarp = (wid & 3) * 32;

    float acc[2][4][4];
    #pragma unroll
    for (int a = 0; a < 2; ++a)
        #pragma unroll
        for (int b = 0; b < 4; ++b)
            #pragma unroll
            for (int c = 0; c < 4; ++c) acc[a][b][c] = 0.f;

    const uint32_t aHi = smem_base + SAHI
        + (mwarp + (lane & 7) + ((lane >> 3) & 1) * 8) * STRB + (lane >> 4) * 16;
    const uint32_t bHi = smem_base + SBHI
        + (lane & 15) * STRB + (nwarp + (lane >> 4) * 8) * 2;

    #pragma unroll
    for (int k = 0; k < 8; ++k) {
        const uint32_t kofA = k * 32;          // +k16 along A cols = 32B
        const uint32_t kofB = k * 16 * STRB;   // +k16 along B rows
        uint32_t ah[2][4], al[2][4], bh[2][4], bl[2][4];
        ldmx4(ah[0], aHi + kofA);
        ldmx4(ah[1], aHi + 16 * STRB + kofA);
        ldmx4(al[0], aHi + SALO + kofA);
        ldmx4(al[1], aHi + SALO + 16 * STRB + kofA);
        ldmx4t(bh[0], bHi + kofB);             // n0:16
        ldmx4t(bh[1], bHi + kofB + 32);        // n16:32
        ldmx4t(bl[0], bHi + (SBLO - SBHI) + kofB);
        ldmx4t(bl[1], bHi + (SBLO - SBHI) + kofB + 32);
        // pass-major order: 8 independent accumulators between c reuses
        #pragma unroll
        for (int p = 0; p < 3; ++p) {
            #pragma unroll
            for (int m2 = 0; m2 < 2; ++m2) {
                const uint32_t* ap = (p == 2) ? al[m2] : ah[m2];
                #pragma unroll
                for (int j = 0; j < 4; ++j) {
                    const uint32_t* bp = (p == 1) ? &bl[j >> 1][(j & 1) * 2]
                                                  : &bh[j >> 1][(j & 1) * 2];
                    mma16816(acc[m2][j], ap, bp);
                }
            }
        }
    }

    // ---- epilogue: direct scatter to y ----
    #pragma unroll
    for (int m2 = 0; m2 < 2; ++m2) {
        const int rbase = mwarp + 16 * m2 + (lane >> 2);
        #pragma unroll
        for (int h = 0; h < 2; ++h) {
            const int mi_l = rbase + 8 * h;
            if (mi_l < valid) {
                const int mi = mi0 + mi_l;
                const int r  = mi / D;
                const int i  = mi - r * D;
                float* yr = y + ((size_t)(row_begin + r) * 128) * D + i;
                #pragma unroll
                for (int nb = 0; nb < 4; ++nb) {
                    const int o = nwarp + 8 * nb + 2 * (lane & 3);
                    yr[(size_t)o * D]       = acc[m2][nb][2 * h + 0];
                    yr[(size_t)(o + 1) * D] = acc[m2][nb][2 * h + 1];
                }
            }
        }
    }
}

__global__ __launch_bounds__(256, 2)
void ilin_mma(const float* __restrict__ x0, const float* __restrict__ x1,
              const float* __restrict__ x2, const float* __restrict__ w,
              const int* __restrict__ rep, float* __restrict__ y)
{
    extern __shared__ char smem[];
    const uint32_t smem_base = smem_u32(smem);
    const int g = blockIdx.x;
    const int z = blockIdx.y;   // 0-1: d1 | 2-7: d3 | 8-17: d5

    const float* wg = w + (size_t)g * 49152;
    if (z < 2) {
        run_tile<1>(smem, smem_base, x0, wg, rep, y, g, z);
    } else if (z < 8) {
        run_tile<3>(smem, smem_base, x1, wg + 16384, rep,
                    y + (size_t)N_ROWS * 128, g, z - 2);
    } else {
        run_tile<5>(smem, smem_base, x2, wg + 32768, rep,
                    y + (size_t)N_ROWS * 512, g, z - 8);
    }
}

extern "C" void kernel_launch(void* const* d_in, const int* in_sizes, int n_in,
                              void* d_out, int out_size)
{
    const float* x0  = (const float*)d_in[0];   // (N, 128, 1)
    const float* x1  = (const float*)d_in[1];   // (N, 128, 3)
    const float* x2  = (const float*)d_in[2];   // (N, 128, 5)
    const float* w   = (const float*)d_in[3];   // (32, 49152)
    const int*   rep = (const int*)d_in[4];     // (32,)
    float* y = (float*)d_out;

    cudaFuncSetAttribute(ilin_mma, cudaFuncAttributeMaxDynamicSharedMemorySize, SMEM_GEMM);
    ilin_mma<<<dim3(G_NUM, 18), 256, SMEM_GEMM>>>(x0, x1, x2, w, rep, y);
}